// round 6
// baseline (speedup 1.0000x reference)
#include <cuda_runtime.h>
#include <cuda_bf16.h>
#include <math.h>
#include <stdint.h>

// Problem constants
#define Bn   32
#define DQ   512
#define DK   512
#define NK   16
#define Hn   8
#define Tt   12
#define Nn   207
#define Cc   64
#define TNC  (Tt*Nn*Cc)      // 158976
#define Mrows (Bn*NK)        // 512
#define Ncols (Hn*DQ)        // 4096
#define NXB  32              // col blocks (4096/128)
#define NYB  8               // row blocks (512/64)
#define NBLK (NXB*NYB)       // 256

__device__ float g_part[NXB * Mrows];  // per-colblock logits partials
__device__ float g_att[Mrows];         // softmax weights
__device__ unsigned g_cnt = 0;         // completion counter (wraps mod NBLK)

// ---------------------------------------------------------------------------
__device__ __forceinline__ void mma_tf32(float* c, const uint32_t* a,
                                         uint32_t b0, uint32_t b1) {
    asm volatile(
        "mma.sync.aligned.m16n8k8.row.col.f32.tf32.tf32.f32 "
        "{%0,%1,%2,%3}, {%4,%5,%6,%7}, {%8,%9}, {%0,%1,%2,%3};"
        : "+f"(c[0]), "+f"(c[1]), "+f"(c[2]), "+f"(c[3])
        : "r"(a[0]), "r"(a[1]), "r"(a[2]), "r"(a[3]), "r"(b0), "r"(b1));
}

__device__ __forceinline__ void cp_async16(uint32_t smem_addr, const void* gptr) {
    asm volatile("cp.async.cg.shared.global [%0], [%1], 16;"
                 :: "r"(smem_addr), "l"(gptr));
}

// ---------------------------------------------------------------------------
// Kernel A: tf32 GEMM + fused epilogue + last-block softmax.
// BM=64, BN=128, BK=32; 256 threads (2x4 warps), warp tile 32x32.
// Grid 256 blocks -> ~2 CTAs/SM for latency hiding.
// A loaded direct from keys (fused transpose, XOR-swizzled), cp.async 2-stage.
// ---------------------------------------------------------------------------
#define SSTR 36
#define A_TILE_F 2048
#define B_TILE_F (128 * SSTR)
#define GEMM_SMEM_F (2*A_TILE_F + 2*B_TILE_F + 4*128 + 128 + 64 + 512)
#define GEMM_SMEM_BYTES (GEMM_SMEM_F * 4)

__global__ __launch_bounds__(256, 2)
void gemm_att_tc(const float* __restrict__ keys, const float* __restrict__ W,
                 const float* __restrict__ bias, const float* __restrict__ query,
                 float* __restrict__ part, float* __restrict__ att) {
    extern __shared__ float smem[];
    float* As    = smem;                      // 2 * 2048 [bloc*512 + d*16 + k] swizzled
    float* Bs    = As + 2 * A_TILE_F;         // 2 * 4608 [n*36 + d]
    float* Qs    = Bs + 2 * B_TILE_F;         // 4*128
    float* biasS = Qs + 4 * 128;              // 128
    float* partS = biasS + 128;               // 64
    float* redS  = partS + 64;                // 512 (last-block reduction)

    int tid  = threadIdx.x;
    int lane = tid & 31;
    int warp = tid >> 5;
    int warp_m = warp >> 2;        // 0..1 (32 rows)
    int warp_n = warp & 3;         // 0..3 (32 cols)
    int g   = lane >> 2;           // 0..7
    int tig = lane & 3;            // 0..3
    int swz = (tig & 2) << 2;

    int c0 = blockIdx.x * 128;
    int m0 = blockIdx.y * 64;
    int q0 = c0 & (DQ - 1);
    int b0 = m0 >> 4;              // 4 batches per 64 rows

    uint32_t sA = (uint32_t)__cvta_generic_to_shared(As);
    uint32_t sB = (uint32_t)__cvta_generic_to_shared(Bs);

    for (int i = tid; i < 4 * 128; i += 256)
        Qs[i] = query[(b0 + (i >> 7)) * DQ + q0 + (i & 127)];
    if (tid < 128) biasS[tid] = bias[c0 + tid];
    if (tid < 64)  partS[tid] = 0.0f;

    // A: 512 16B-chunks/tile (2/thread); B: 1024 chunks (4/thread)
    auto issue_tile = [&](int kt, int s) {
        uint32_t aBase = sA + (uint32_t)(s * A_TILE_F) * 4;
        uint32_t bBase = sB + (uint32_t)(s * B_TILE_F) * 4;
        #pragma unroll
        for (int i = 0; i < 2; i++) {
            int flat = i * 256 + tid;          // 0..511
            int bloc = flat >> 7;              // 0..3
            int rem  = flat & 127;
            int dl   = rem >> 2;               // 0..31
            int kkc  = rem & 3;                // 0..3
            const float* src = keys + (size_t)(b0 + bloc) * (DK * NK)
                             + (size_t)(kt + dl) * NK + kkc * 4;
            int woff = bloc * 512 + dl * 16 + ((kkc * 4) ^ ((dl & 2) << 2));
            cp_async16(aBase + (uint32_t)woff * 4, src);
        }
        #pragma unroll
        for (int i = 0; i < 4; i++) {
            int flat = i * 256 + tid;
            int r = flat >> 3, cc = flat & 7;
            const float* src = W + (size_t)(c0 + r) * DK + kt + cc * 4;
            cp_async16(bBase + (uint32_t)(r * SSTR + cc * 4) * 4, src);
        }
        asm volatile("cp.async.commit_group;");
    };

    float acc[2][4][4] = {};
    issue_tile(0, 0);

    for (int it = 0; it < 16; it++) {
        int buf = it & 1;
        if (it < 15) {
            issue_tile((it + 1) * 32, buf ^ 1);
            asm volatile("cp.async.wait_group 1;");
        } else {
            asm volatile("cp.async.wait_group 0;");
        }
        __syncthreads();

        const float* Ab = As + buf * A_TILE_F;
        const float* Bb = Bs + buf * B_TILE_F;

        #pragma unroll
        for (int ks = 0; ks < 4; ks++) {
            int k = ks * 8 + tig;
            uint32_t a[2][4];
            #pragma unroll
            for (int mt = 0; mt < 2; mt++) {
                int bloc = warp_m * 2 + mt;
                const float* ab = &Ab[bloc * 512];
                a[mt][0] = __float_as_uint(ab[(k    ) * 16 + ( g      ^ swz)]);
                a[mt][1] = __float_as_uint(ab[(k    ) * 16 + ((g + 8) ^ swz)]);
                a[mt][2] = __float_as_uint(ab[(k + 4) * 16 + ( g      ^ swz)]);
                a[mt][3] = __float_as_uint(ab[(k + 4) * 16 + ((g + 8) ^ swz)]);
            }
            #pragma unroll
            for (int nt = 0; nt < 4; nt++) {
                int nbase = warp_n * 32 + nt * 8 + g;
                uint32_t b0r = __float_as_uint(Bb[nbase * SSTR + k    ]);
                uint32_t b1r = __float_as_uint(Bb[nbase * SSTR + k + 4]);
                #pragma unroll
                for (int mt = 0; mt < 2; mt++)
                    mma_tf32(acc[mt][nt], a[mt], b0r, b1r);
            }
        }
        __syncthreads();
    }

    // Epilogue: bias + relu + Q-weight, reduce per row
    #pragma unroll
    for (int mt = 0; mt < 2; mt++) {
        int mlo = warp_m * 32 + mt * 16 + g;
        int mhi = mlo + 8;
        const float* q_lo = &Qs[(mlo >> 4) * 128];
        const float* q_hi = &Qs[(mhi >> 4) * 128];
        float p_lo = 0.0f, p_hi = 0.0f;
        #pragma unroll
        for (int nt = 0; nt < 4; nt++) {
            int cl = warp_n * 32 + nt * 8 + 2 * tig;
            float bi0 = biasS[cl], bi1 = biasS[cl + 1];
            p_lo = fmaf(fmaxf(acc[mt][nt][0] + bi0, 0.0f), q_lo[cl],     p_lo);
            p_lo = fmaf(fmaxf(acc[mt][nt][1] + bi1, 0.0f), q_lo[cl + 1], p_lo);
            p_hi = fmaf(fmaxf(acc[mt][nt][2] + bi0, 0.0f), q_hi[cl],     p_hi);
            p_hi = fmaf(fmaxf(acc[mt][nt][3] + bi1, 0.0f), q_hi[cl + 1], p_hi);
        }
        p_lo += __shfl_xor_sync(0xffffffffu, p_lo, 1);
        p_lo += __shfl_xor_sync(0xffffffffu, p_lo, 2);
        p_hi += __shfl_xor_sync(0xffffffffu, p_hi, 1);
        p_hi += __shfl_xor_sync(0xffffffffu, p_hi, 2);
        if (tig == 0) {
            atomicAdd(&partS[mlo], p_lo);
            atomicAdd(&partS[mhi], p_hi);
        }
    }
    __syncthreads();
    if (tid < 64) part[blockIdx.x * Mrows + m0 + tid] = partS[tid];

    // ---- last block: reduce partials + softmax (saves a kernel launch) ----
    __threadfence();
    __shared__ unsigned s_last;
    if (tid == 0) {
        unsigned old;
        asm volatile("atom.global.inc.u32 %0, [%1], %2;"
                     : "=r"(old) : "l"(&g_cnt), "r"((unsigned)(NBLK - 1)) : "memory");
        s_last = (old == NBLK - 1);
    }
    __syncthreads();
    if (!s_last) return;

    for (int m = tid; m < Mrows; m += 256) {
        float s = 0.0f;
        #pragma unroll
        for (int x = 0; x < NXB; x++) s += part[x * Mrows + m];
        redS[m] = s;
    }
    __syncthreads();
    if (tid < Bn) {
        const float scale = 1.0f / (8.0f * 22.62741699796952f);  // 1/(H*sqrt(512))
        float v[NK], mx = -1e30f;
        #pragma unroll
        for (int k = 0; k < NK; k++) { v[k] = redS[tid * NK + k] * scale; mx = fmaxf(mx, v[k]); }
        float z = 0.0f;
        #pragma unroll
        for (int k = 0; k < NK; k++) { v[k] = __expf(v[k] - mx); z += v[k]; }
        float inv = 1.0f / z;
        #pragma unroll
        for (int k = 0; k < NK; k++) att[tid * NK + k] = v[k] * inv;
    }
}

// ---------------------------------------------------------------------------
// Kernel C: att-weighted V reduction. 2 contiguous outputs/thread
// (8 LDG.128 in flight, 128B dense per thread).
// ---------------------------------------------------------------------------
__global__ __launch_bounds__(256)
void weighted_v_kernel(const float* __restrict__ V, const float* __restrict__ att,
                       float* __restrict__ out) {
    __shared__ float aw[NK];
    int b = blockIdx.y;
    if (threadIdx.x < NK) aw[threadIdx.x] = att[b * NK + threadIdx.x];
    __syncthreads();

    int i0 = (blockIdx.x * 256 + threadIdx.x) * 2;
    if (i0 >= TNC) return;
    const float4* v4 = (const float4*)(V + ((size_t)b * TNC + i0) * NK);
    float4 p0 = v4[0], p1 = v4[1], p2 = v4[2], p3 = v4[3];
    float4 q0 = v4[4], q1 = v4[5], q2 = v4[6], q3 = v4[7];

    float w0 = aw[0],  w1 = aw[1],  w2 = aw[2],  w3 = aw[3];
    float w4 = aw[4],  w5 = aw[5],  w6 = aw[6],  w7 = aw[7];
    float w8 = aw[8],  w9 = aw[9],  wa = aw[10], wb = aw[11];
    float wc = aw[12], wd = aw[13], we = aw[14], wf = aw[15];

    float s0;
    s0  = p0.x * w0 + p0.y * w1 + p0.z * w2 + p0.w * w3;
    s0 += p1.x * w4 + p1.y * w5 + p1.z * w6 + p1.w * w7;
    s0 += p2.x * w8 + p2.y * w9 + p2.z * wa + p2.w * wb;
    s0 += p3.x * wc + p3.y * wd + p3.z * we + p3.w * wf;
    float s1;
    s1  = q0.x * w0 + q0.y * w1 + q0.z * w2 + q0.w * w3;
    s1 += q1.x * w4 + q1.y * w5 + q1.z * w6 + q1.w * w7;
    s1 += q2.x * w8 + q2.y * w9 + q2.z * wa + q2.w * wb;
    s1 += q3.x * wc + q3.y * wd + q3.z * we + q3.w * wf;

    *(float2*)(out + (size_t)b * TNC + i0) = make_float2(s0, s1);
}

// ---------------------------------------------------------------------------
extern "C" void kernel_launch(void* const* d_in, const int* in_sizes, int n_in,
                              void* d_out, int out_size) {
    const float *query = nullptr, *keys = nullptr, *V = nullptr,
                *W = nullptr, *bias = nullptr;
    for (int i = 0; i < n_in; i++) {
        switch (in_sizes[i]) {
            case Bn * DQ:            query = (const float*)d_in[i]; break;
            case Bn * DK * NK:       keys  = (const float*)d_in[i]; break;
            case Bn * TNC * NK:      V     = (const float*)d_in[i]; break;
            case Hn * DQ * DK:       W     = (const float*)d_in[i]; break;
            case Hn * DQ:            bias  = (const float*)d_in[i]; break;
            default: break;
        }
    }
    float* out = (float*)d_out;

    float* part; cudaGetSymbolAddress((void**)&part, g_part);
    float* att;  cudaGetSymbolAddress((void**)&att,  g_att);

    cudaFuncSetAttribute(gemm_att_tc,
                         cudaFuncAttributeMaxDynamicSharedMemorySize,
                         GEMM_SMEM_BYTES);

    dim3 gridA(NXB, NYB);                   // (32, 8) = 256 blocks
    gemm_att_tc<<<gridA, 256, GEMM_SMEM_BYTES>>>(keys, W, bias, query, part, att);

    dim3 gridC((TNC / 2 + 255) / 256, Bn);  // (311, 32)
    weighted_v_kernel<<<gridC, 256>>>(V, att, out);
}

// round 7
// speedup vs baseline: 1.2750x; 1.2750x over previous
#include <cuda_runtime.h>
#include <cuda_bf16.h>
#include <math.h>
#include <stdint.h>

// Problem constants
#define Bn   32
#define DQ   512
#define DK   512
#define NK   16
#define Hn   8
#define Tt   12
#define Nn   207
#define Cc   64
#define TNC  (Tt*Nn*Cc)      // 158976
#define Mrows (Bn*NK)        // 512
#define Ncols (Hn*DQ)        // 4096
#define NXB  32              // col blocks (4096/128)
#define NYB  8               // row blocks (512/64)
#define NBLK (NXB*NYB)       // 256

__device__ float g_part[NXB * Mrows];  // per-colblock logits partials
__device__ float g_att[Mrows];         // softmax weights
__device__ unsigned g_cnt = 0;         // completion counter (wraps mod NBLK)

// ---------------------------------------------------------------------------
__device__ __forceinline__ void mma_tf32(float* c, const uint32_t* a,
                                         uint32_t b0, uint32_t b1) {
    asm volatile(
        "mma.sync.aligned.m16n8k8.row.col.f32.tf32.tf32.f32 "
        "{%0,%1,%2,%3}, {%4,%5,%6,%7}, {%8,%9}, {%0,%1,%2,%3};"
        : "+f"(c[0]), "+f"(c[1]), "+f"(c[2]), "+f"(c[3])
        : "r"(a[0]), "r"(a[1]), "r"(a[2]), "r"(a[3]), "r"(b0), "r"(b1));
}

__device__ __forceinline__ void cp_async16(uint32_t smem_addr, const void* gptr) {
    asm volatile("cp.async.cg.shared.global [%0], [%1], 16;"
                 :: "r"(smem_addr), "l"(gptr));
}

// ---------------------------------------------------------------------------
// Kernel A: tf32 GEMM + fused epilogue + last-block softmax.
// BM=64, BN=128, BK=32; 256 threads (2x4 warps), warp tile 32x32.
// 3-stage cp.async pipeline: prefetch distance 2 tiles covers L2 latency.
// ---------------------------------------------------------------------------
#define SSTR 36
#define A_TILE_F 2048
#define B_TILE_F (128 * SSTR)
#define NSTAGE 3
#define GEMM_SMEM_F (NSTAGE*(A_TILE_F + B_TILE_F) + 4*128 + 128 + 64 + 512)
#define GEMM_SMEM_BYTES (GEMM_SMEM_F * 4)

__global__ __launch_bounds__(256, 2)
void gemm_att_tc(const float* __restrict__ keys, const float* __restrict__ W,
                 const float* __restrict__ bias, const float* __restrict__ query,
                 float* __restrict__ part, float* __restrict__ att) {
    extern __shared__ float smem[];
    float* As    = smem;                          // 3 * 2048 [bloc*512 + d*16 + k] swz
    float* Bs    = As + NSTAGE * A_TILE_F;        // 3 * 4608 [n*36 + d]
    float* Qs    = Bs + NSTAGE * B_TILE_F;        // 4*128
    float* biasS = Qs + 4 * 128;                  // 128
    float* partS = biasS + 128;                   // 64
    float* redS  = partS + 64;                    // 512

    int tid  = threadIdx.x;
    int lane = tid & 31;
    int warp = tid >> 5;
    int warp_m = warp >> 2;        // 0..1 (32 rows)
    int warp_n = warp & 3;         // 0..3 (32 cols)
    int g   = lane >> 2;           // 0..7
    int tig = lane & 3;            // 0..3
    int swz = (tig & 2) << 2;

    int c0 = blockIdx.x * 128;
    int m0 = blockIdx.y * 64;
    int q0 = c0 & (DQ - 1);
    int b0 = m0 >> 4;              // 4 batches per 64 rows

    uint32_t sA = (uint32_t)__cvta_generic_to_shared(As);
    uint32_t sB = (uint32_t)__cvta_generic_to_shared(Bs);

    for (int i = tid; i < 4 * 128; i += 256)
        Qs[i] = query[(b0 + (i >> 7)) * DQ + q0 + (i & 127)];
    if (tid < 128) biasS[tid] = bias[c0 + tid];
    if (tid < 64)  partS[tid] = 0.0f;

    auto issue_tile = [&](int kt, int s) {
        uint32_t aBase = sA + (uint32_t)(s * A_TILE_F) * 4;
        uint32_t bBase = sB + (uint32_t)(s * B_TILE_F) * 4;
        #pragma unroll
        for (int i = 0; i < 2; i++) {
            int flat = i * 256 + tid;          // 0..511
            int bloc = flat >> 7;              // 0..3
            int rem  = flat & 127;
            int dl   = rem >> 2;               // 0..31
            int kkc  = rem & 3;                // 0..3
            const float* src = keys + (size_t)(b0 + bloc) * (DK * NK)
                             + (size_t)(kt + dl) * NK + kkc * 4;
            int woff = bloc * 512 + dl * 16 + ((kkc * 4) ^ ((dl & 2) << 2));
            cp_async16(aBase + (uint32_t)woff * 4, src);
        }
        #pragma unroll
        for (int i = 0; i < 4; i++) {
            int flat = i * 256 + tid;
            int r = flat >> 3, cc = flat & 7;
            const float* src = W + (size_t)(c0 + r) * DK + kt + cc * 4;
            cp_async16(bBase + (uint32_t)(r * SSTR + cc * 4) * 4, src);
        }
        asm volatile("cp.async.commit_group;");
    };

    float acc[2][4][4] = {};
    issue_tile(0, 0);
    issue_tile(32, 1);

    for (int it = 0; it < 16; it++) {
        if (it) __syncthreads();           // fence reads of it-1 before reuse of its stage
        if (it < 14) issue_tile((it + 2) * 32, (it + 2) % NSTAGE);
        if (it < 14)       asm volatile("cp.async.wait_group 2;");
        else if (it == 14) asm volatile("cp.async.wait_group 1;");
        else               asm volatile("cp.async.wait_group 0;");
        __syncthreads();                   // copies visible block-wide

        const float* Ab = As + (it % NSTAGE) * A_TILE_F;
        const float* Bb = Bs + (it % NSTAGE) * B_TILE_F;

        #pragma unroll
        for (int ks = 0; ks < 4; ks++) {
            int k = ks * 8 + tig;
            uint32_t a[2][4];
            #pragma unroll
            for (int mt = 0; mt < 2; mt++) {
                int bloc = warp_m * 2 + mt;
                const float* ab = &Ab[bloc * 512];
                a[mt][0] = __float_as_uint(ab[(k    ) * 16 + ( g      ^ swz)]);
                a[mt][1] = __float_as_uint(ab[(k    ) * 16 + ((g + 8) ^ swz)]);
                a[mt][2] = __float_as_uint(ab[(k + 4) * 16 + ( g      ^ swz)]);
                a[mt][3] = __float_as_uint(ab[(k + 4) * 16 + ((g + 8) ^ swz)]);
            }
            #pragma unroll
            for (int nt = 0; nt < 4; nt++) {
                int nbase = warp_n * 32 + nt * 8 + g;
                uint32_t b0r = __float_as_uint(Bb[nbase * SSTR + k    ]);
                uint32_t b1r = __float_as_uint(Bb[nbase * SSTR + k + 4]);
                #pragma unroll
                for (int mt = 0; mt < 2; mt++)
                    mma_tf32(acc[mt][nt], a[mt], b0r, b1r);
            }
        }
    }
    __syncthreads();

    // Epilogue: bias + relu + Q-weight, reduce per row
    #pragma unroll
    for (int mt = 0; mt < 2; mt++) {
        int mlo = warp_m * 32 + mt * 16 + g;
        int mhi = mlo + 8;
        const float* q_lo = &Qs[(mlo >> 4) * 128];
        const float* q_hi = &Qs[(mhi >> 4) * 128];
        float p_lo = 0.0f, p_hi = 0.0f;
        #pragma unroll
        for (int nt = 0; nt < 4; nt++) {
            int cl = warp_n * 32 + nt * 8 + 2 * tig;
            float bi0 = biasS[cl], bi1 = biasS[cl + 1];
            p_lo = fmaf(fmaxf(acc[mt][nt][0] + bi0, 0.0f), q_lo[cl],     p_lo);
            p_lo = fmaf(fmaxf(acc[mt][nt][1] + bi1, 0.0f), q_lo[cl + 1], p_lo);
            p_hi = fmaf(fmaxf(acc[mt][nt][2] + bi0, 0.0f), q_hi[cl],     p_hi);
            p_hi = fmaf(fmaxf(acc[mt][nt][3] + bi1, 0.0f), q_hi[cl + 1], p_hi);
        }
        p_lo += __shfl_xor_sync(0xffffffffu, p_lo, 1);
        p_lo += __shfl_xor_sync(0xffffffffu, p_lo, 2);
        p_hi += __shfl_xor_sync(0xffffffffu, p_hi, 1);
        p_hi += __shfl_xor_sync(0xffffffffu, p_hi, 2);
        if (tig == 0) {
            atomicAdd(&partS[mlo], p_lo);
            atomicAdd(&partS[mhi], p_hi);
        }
    }
    __syncthreads();
    if (tid < 64) part[blockIdx.x * Mrows + m0 + tid] = partS[tid];

    // ---- last block: reduce partials + softmax ----
    __threadfence();
    __shared__ unsigned s_last;
    if (tid == 0) {
        unsigned old;
        asm volatile("atom.global.inc.u32 %0, [%1], %2;"
                     : "=r"(old) : "l"(&g_cnt), "r"((unsigned)(NBLK - 1)) : "memory");
        s_last = (old == NBLK - 1);
    }
    __syncthreads();
    if (!s_last) return;

    for (int m = tid; m < Mrows; m += 256) {
        float s = 0.0f;
        #pragma unroll
        for (int x = 0; x < NXB; x++) s += part[x * Mrows + m];
        redS[m] = s;
    }
    __syncthreads();
    if (tid < Bn) {
        const float scale = 1.0f / (8.0f * 22.62741699796952f);  // 1/(H*sqrt(512))
        float v[NK], mx = -1e30f;
        #pragma unroll
        for (int k = 0; k < NK; k++) { v[k] = redS[tid * NK + k] * scale; mx = fmaxf(mx, v[k]); }
        float z = 0.0f;
        #pragma unroll
        for (int k = 0; k < NK; k++) { v[k] = __expf(v[k] - mx); z += v[k]; }
        float inv = 1.0f / z;
        #pragma unroll
        for (int k = 0; k < NK; k++) att[tid * NK + k] = v[k] * inv;
    }
}

// ---------------------------------------------------------------------------
// Kernel C: att-weighted V reduction — R5-proven 1 elem/thread body.
// (2 elem/thread regressed: 32 L1 lines per LDG wavefront throttled L1tex.)
// ---------------------------------------------------------------------------
__global__ __launch_bounds__(256, 8)
void weighted_v_kernel(const float* __restrict__ V, const float* __restrict__ att,
                       float* __restrict__ out) {
    __shared__ float aw[NK];
    int b = blockIdx.y;
    if (threadIdx.x < NK) aw[threadIdx.x] = att[b * NK + threadIdx.x];
    __syncthreads();
    int i = blockIdx.x * blockDim.x + threadIdx.x;
    if (i >= TNC) return;
    const float4* v4 = (const float4*)(V + ((size_t)b * TNC + i) * NK);
    float4 p0 = v4[0], p1 = v4[1], p2 = v4[2], p3 = v4[3];
    float s;
    s  = p0.x * aw[0]  + p0.y * aw[1]  + p0.z * aw[2]  + p0.w * aw[3];
    s += p1.x * aw[4]  + p1.y * aw[5]  + p1.z * aw[6]  + p1.w * aw[7];
    s += p2.x * aw[8]  + p2.y * aw[9]  + p2.z * aw[10] + p2.w * aw[11];
    s += p3.x * aw[12] + p3.y * aw[13] + p3.z * aw[14] + p3.w * aw[15];
    out[(size_t)b * TNC + i] = s;
}

// ---------------------------------------------------------------------------
extern "C" void kernel_launch(void* const* d_in, const int* in_sizes, int n_in,
                              void* d_out, int out_size) {
    const float *query = nullptr, *keys = nullptr, *V = nullptr,
                *W = nullptr, *bias = nullptr;
    for (int i = 0; i < n_in; i++) {
        switch (in_sizes[i]) {
            case Bn * DQ:            query = (const float*)d_in[i]; break;
            case Bn * DK * NK:       keys  = (const float*)d_in[i]; break;
            case Bn * TNC * NK:      V     = (const float*)d_in[i]; break;
            case Hn * DQ * DK:       W     = (const float*)d_in[i]; break;
            case Hn * DQ:            bias  = (const float*)d_in[i]; break;
            default: break;
        }
    }
    float* out = (float*)d_out;

    float* part; cudaGetSymbolAddress((void**)&part, g_part);
    float* att;  cudaGetSymbolAddress((void**)&att,  g_att);

    cudaFuncSetAttribute(gemm_att_tc,
                         cudaFuncAttributeMaxDynamicSharedMemorySize,
                         GEMM_SMEM_BYTES);

    dim3 gridA(NXB, NYB);                   // (32, 8) = 256 blocks
    gemm_att_tc<<<gridA, 256, GEMM_SMEM_BYTES>>>(keys, W, bias, query, part, att);

    dim3 gridC(TNC / 256, Bn);              // (621, 32)
    weighted_v_kernel<<<gridC, 256>>>(V, att, out);
}

// round 8
// speedup vs baseline: 1.3084x; 1.0262x over previous
#include <cuda_runtime.h>
#include <cuda_bf16.h>
#include <math.h>
#include <stdint.h>

// Problem constants
#define Bn   32
#define DQ   512
#define DK   512
#define NK   16
#define Hn   8
#define Tt   12
#define Nn   207
#define Cc   64
#define TNC  (Tt*Nn*Cc)      // 158976
#define Mrows (Bn*NK)        // 512
#define Ncols (Hn*DQ)        // 4096
#define NXB  32              // col blocks (4096/128)
#define NYB  8               // row blocks (512/64)
#define NBLK (NXB*NYB)       // 256

__device__ float g_part[NXB * Mrows];  // per-colblock logits partials
__device__ float g_att[Mrows];         // softmax weights
__device__ unsigned g_cnt = 0;         // completion counter (wraps mod NBLK)

// ---------------------------------------------------------------------------
__device__ __forceinline__ void mma_tf32(float* c, const uint32_t* a,
                                         uint32_t b0, uint32_t b1) {
    asm volatile(
        "mma.sync.aligned.m16n8k8.row.col.f32.tf32.tf32.f32 "
        "{%0,%1,%2,%3}, {%4,%5,%6,%7}, {%8,%9}, {%0,%1,%2,%3};"
        : "+f"(c[0]), "+f"(c[1]), "+f"(c[2]), "+f"(c[3])
        : "r"(a[0]), "r"(a[1]), "r"(a[2]), "r"(a[3]), "r"(b0), "r"(b1));
}

__device__ __forceinline__ void cp_async16(uint32_t smem_addr, const void* gptr) {
    asm volatile("cp.async.cg.shared.global [%0], [%1], 16;"
                 :: "r"(smem_addr), "l"(gptr));
}

// ---------------------------------------------------------------------------
// Kernel A: tf32 GEMM + fused epilogue + last-block softmax.
// BM=64, BN=128, BK=64 -> only 8 barrier-to-barrier sections (chain-limited).
// 256 threads (2x4 warps), warp tile 32x32, 2-stage cp.async.
// smem/stage: A 64x64 (keys-native swizzled) + B 128x68 -> 2 CTAs/SM, 1 wave.
// ---------------------------------------------------------------------------
#define BKK  64
#define NIT  (DK / BKK)            // 8
#define SSTR2 68
#define A_TILE_F (64 * 64)         // 4096  [bloc*1024 + d*16 + k] swizzled
#define B_TILE_F (128 * SSTR2)     // 8704  [n*68 + d]
#define GEMM_SMEM_F (2*(A_TILE_F + B_TILE_F) + 4*128 + 128 + 64 + 512)
#define GEMM_SMEM_BYTES (GEMM_SMEM_F * 4)

__global__ __launch_bounds__(256, 2)
void gemm_att_tc(const float* __restrict__ keys, const float* __restrict__ W,
                 const float* __restrict__ bias, const float* __restrict__ query,
                 float* __restrict__ part, float* __restrict__ att) {
    extern __shared__ float smem[];
    float* As    = smem;                          // 2 * 4096
    float* Bs    = As + 2 * A_TILE_F;             // 2 * 8704
    float* Qs    = Bs + 2 * B_TILE_F;             // 4*128
    float* biasS = Qs + 4 * 128;                  // 128
    float* partS = biasS + 128;                   // 64
    float* redS  = partS + 64;                    // 512

    int tid  = threadIdx.x;
    int lane = tid & 31;
    int warp = tid >> 5;
    int warp_m = warp >> 2;        // 0..1 (32 rows)
    int warp_n = warp & 3;         // 0..3 (32 cols)
    int g   = lane >> 2;           // 0..7
    int tig = lane & 3;            // 0..3
    int swz = (tig & 2) << 2;

    int c0 = blockIdx.x * 128;
    int m0 = blockIdx.y * 64;
    int q0 = c0 & (DQ - 1);
    int b0 = m0 >> 4;              // 4 batches per 64 rows

    uint32_t sA = (uint32_t)__cvta_generic_to_shared(As);
    uint32_t sB = (uint32_t)__cvta_generic_to_shared(Bs);

    for (int i = tid; i < 4 * 128; i += 256)
        Qs[i] = query[(b0 + (i >> 7)) * DQ + q0 + (i & 127)];
    if (tid < 128) biasS[tid] = bias[c0 + tid];
    if (tid < 64)  partS[tid] = 0.0f;

    // A: 1024 16B-chunks/tile (4/thread); B: 2048 chunks (8/thread)
    auto issue_tile = [&](int kt, int s) {
        uint32_t aBase = sA + (uint32_t)(s * A_TILE_F) * 4;
        uint32_t bBase = sB + (uint32_t)(s * B_TILE_F) * 4;
        #pragma unroll
        for (int i = 0; i < 4; i++) {
            int flat = i * 256 + tid;          // 0..1023
            int bloc = flat >> 8;              // 0..3
            int rem  = flat & 255;
            int dl   = rem >> 2;               // 0..63
            int kkc  = rem & 3;                // 0..3
            const float* src = keys + (size_t)(b0 + bloc) * (DK * NK)
                             + (size_t)(kt + dl) * NK + kkc * 4;
            int woff = bloc * 1024 + dl * 16 + ((kkc * 4) ^ ((dl & 2) << 2));
            cp_async16(aBase + (uint32_t)woff * 4, src);
        }
        #pragma unroll
        for (int i = 0; i < 8; i++) {
            int flat = i * 256 + tid;          // 0..2047
            int r = flat >> 4, cc = flat & 15;
            const float* src = W + (size_t)(c0 + r) * DK + kt + cc * 4;
            cp_async16(bBase + (uint32_t)(r * SSTR2 + cc * 4) * 4, src);
        }
        asm volatile("cp.async.commit_group;");
    };

    float acc[2][4][4] = {};
    issue_tile(0, 0);

    for (int it = 0; it < NIT; it++) {
        int buf = it & 1;
        if (it < NIT - 1) {
            issue_tile((it + 1) * BKK, buf ^ 1);
            asm volatile("cp.async.wait_group 1;");
        } else {
            asm volatile("cp.async.wait_group 0;");
        }
        __syncthreads();

        const float* Ab = As + buf * A_TILE_F;
        const float* Bb = Bs + buf * B_TILE_F;

        #pragma unroll
        for (int ks = 0; ks < BKK / 8; ks++) {
            int k = ks * 8 + tig;              // d in [0,64); k&2 == tig&2
            uint32_t a[2][4];
            #pragma unroll
            for (int mt = 0; mt < 2; mt++) {
                int bloc = warp_m * 2 + mt;
                const float* ab = &Ab[bloc * 1024];
                a[mt][0] = __float_as_uint(ab[(k    ) * 16 + ( g      ^ swz)]);
                a[mt][1] = __float_as_uint(ab[(k    ) * 16 + ((g + 8) ^ swz)]);
                a[mt][2] = __float_as_uint(ab[(k + 4) * 16 + ( g      ^ swz)]);
                a[mt][3] = __float_as_uint(ab[(k + 4) * 16 + ((g + 8) ^ swz)]);
            }
            #pragma unroll
            for (int nt = 0; nt < 4; nt++) {
                int nbase = warp_n * 32 + nt * 8 + g;
                uint32_t b0r = __float_as_uint(Bb[nbase * SSTR2 + k    ]);
                uint32_t b1r = __float_as_uint(Bb[nbase * SSTR2 + k + 4]);
                #pragma unroll
                for (int mt = 0; mt < 2; mt++)
                    mma_tf32(acc[mt][nt], a[mt], b0r, b1r);
            }
        }
        __syncthreads();
    }

    // Epilogue: bias + relu + Q-weight, reduce per row
    #pragma unroll
    for (int mt = 0; mt < 2; mt++) {
        int mlo = warp_m * 32 + mt * 16 + g;
        int mhi = mlo + 8;
        const float* q_lo = &Qs[(mlo >> 4) * 128];
        const float* q_hi = &Qs[(mhi >> 4) * 128];
        float p_lo = 0.0f, p_hi = 0.0f;
        #pragma unroll
        for (int nt = 0; nt < 4; nt++) {
            int cl = warp_n * 32 + nt * 8 + 2 * tig;
            float bi0 = biasS[cl], bi1 = biasS[cl + 1];
            p_lo = fmaf(fmaxf(acc[mt][nt][0] + bi0, 0.0f), q_lo[cl],     p_lo);
            p_lo = fmaf(fmaxf(acc[mt][nt][1] + bi1, 0.0f), q_lo[cl + 1], p_lo);
            p_hi = fmaf(fmaxf(acc[mt][nt][2] + bi0, 0.0f), q_hi[cl],     p_hi);
            p_hi = fmaf(fmaxf(acc[mt][nt][3] + bi1, 0.0f), q_hi[cl + 1], p_hi);
        }
        p_lo += __shfl_xor_sync(0xffffffffu, p_lo, 1);
        p_lo += __shfl_xor_sync(0xffffffffu, p_lo, 2);
        p_hi += __shfl_xor_sync(0xffffffffu, p_hi, 1);
        p_hi += __shfl_xor_sync(0xffffffffu, p_hi, 2);
        if (tig == 0) {
            atomicAdd(&partS[mlo], p_lo);
            atomicAdd(&partS[mhi], p_hi);
        }
    }
    __syncthreads();
    if (tid < 64) part[blockIdx.x * Mrows + m0 + tid] = partS[tid];

    // ---- last block: reduce partials + softmax ----
    __threadfence();
    __shared__ unsigned s_last;
    if (tid == 0) {
        unsigned old;
        asm volatile("atom.global.inc.u32 %0, [%1], %2;"
                     : "=r"(old) : "l"(&g_cnt), "r"((unsigned)(NBLK - 1)) : "memory");
        s_last = (old == NBLK - 1);
    }
    __syncthreads();
    if (!s_last) return;

    for (int m = tid; m < Mrows; m += 256) {
        float s = 0.0f;
        #pragma unroll
        for (int x = 0; x < NXB; x++) s += part[x * Mrows + m];
        redS[m] = s;
    }
    __syncthreads();
    if (tid < Bn) {
        const float scale = 1.0f / (8.0f * 22.62741699796952f);  // 1/(H*sqrt(512))
        float v[NK], mx = -1e30f;
        #pragma unroll
        for (int k = 0; k < NK; k++) { v[k] = redS[tid * NK + k] * scale; mx = fmaxf(mx, v[k]); }
        float z = 0.0f;
        #pragma unroll
        for (int k = 0; k < NK; k++) { v[k] = __expf(v[k] - mx); z += v[k]; }
        float inv = 1.0f / z;
        #pragma unroll
        for (int k = 0; k < NK; k++) att[tid * NK + k] = v[k] * inv;
    }
}

// ---------------------------------------------------------------------------
// Kernel C: att-weighted V reduction — exact R1 config (best measured: 55.1us,
// 38 regs, occ 60%). No occupancy forcing (higher occ raised L1tex contention).
// ---------------------------------------------------------------------------
__global__ __launch_bounds__(256)
void weighted_v_kernel(const float* __restrict__ V, const float* __restrict__ att,
                       float* __restrict__ out) {
    __shared__ float aw[NK];
    int b = blockIdx.y;
    if (threadIdx.x < NK) aw[threadIdx.x] = att[b * NK + threadIdx.x];
    __syncthreads();
    int i = blockIdx.x * blockDim.x + threadIdx.x;
    if (i >= TNC) return;
    const float4* v4 = (const float4*)(V + ((size_t)b * TNC + i) * NK);
    float4 p0 = v4[0], p1 = v4[1], p2 = v4[2], p3 = v4[3];
    float s;
    s  = p0.x * aw[0]  + p0.y * aw[1]  + p0.z * aw[2]  + p0.w * aw[3];
    s += p1.x * aw[4]  + p1.y * aw[5]  + p1.z * aw[6]  + p1.w * aw[7];
    s += p2.x * aw[8]  + p2.y * aw[9]  + p2.z * aw[10] + p2.w * aw[11];
    s += p3.x * aw[12] + p3.y * aw[13] + p3.z * aw[14] + p3.w * aw[15];
    out[(size_t)b * TNC + i] = s;
}

// ---------------------------------------------------------------------------
extern "C" void kernel_launch(void* const* d_in, const int* in_sizes, int n_in,
                              void* d_out, int out_size) {
    const float *query = nullptr, *keys = nullptr, *V = nullptr,
                *W = nullptr, *bias = nullptr;
    for (int i = 0; i < n_in; i++) {
        switch (in_sizes[i]) {
            case Bn * DQ:            query = (const float*)d_in[i]; break;
            case Bn * DK * NK:       keys  = (const float*)d_in[i]; break;
            case Bn * TNC * NK:      V     = (const float*)d_in[i]; break;
            case Hn * DQ * DK:       W     = (const float*)d_in[i]; break;
            case Hn * DQ:            bias  = (const float*)d_in[i]; break;
            default: break;
        }
    }
    float* out = (float*)d_out;

    float* part; cudaGetSymbolAddress((void**)&part, g_part);
    float* att;  cudaGetSymbolAddress((void**)&att,  g_att);

    cudaFuncSetAttribute(gemm_att_tc,
                         cudaFuncAttributeMaxDynamicSharedMemorySize,
                         GEMM_SMEM_BYTES);

    dim3 gridA(NXB, NYB);                   // (32, 8) = 256 blocks
    gemm_att_tc<<<gridA, 256, GEMM_SMEM_BYTES>>>(keys, W, bias, query, part, att);

    dim3 gridC(TNC / 256, Bn);              // (621, 32)
    weighted_v_kernel<<<gridC, 256>>>(V, att, out);
}